// round 12
// baseline (speedup 1.0000x reference)
#include <cuda_runtime.h>

static constexpr int N = 32768;
static constexpr int C = 1000;
static constexpr int K_RANK = 9830;        // int(N * 0.3), 0-based descending rank
static constexpr int NB = 8192;            // histogram bins
static constexpr int CAP = 128;            // bucket capacity per bin (max obs ~70)
static constexpr unsigned int KEY_BASE = 0x40000000u >> 12;  // bits(2.0f) >> 12

// Row split: kernel 1 handles [0, ROWS_K1); kernel 2's blocks 1..147 handle
// the remaining 9408 rows (2 rows per warp) while block 0 prepares to select.
static constexpr int K2_BLOCKS   = 148;                 // single wave, co-resident
static constexpr int K2_CE       = K2_BLOCKS - 1;       // 147 CE blocks
static constexpr int ROWS_K2     = K2_CE * 32 * 2;      // 9408
static constexpr int ROWS_K1     = N - ROWS_K2;         // 23360
static constexpr int GRID_K1     = ROWS_K1 / 8;         // 2920

__device__ unsigned int g_hist[NB];            // counts / bucket slot counters
__device__ float        g_binsum[NB];          // per-bin CE sums
__device__ unsigned int g_bucket[NB * CAP];    // CE bit patterns by bin
__device__ unsigned int g_done2;               // kernel-2 CE completion counter

// key: 2 exponent bits + 11 mantissa bits over [2.0, 32.0), clamped tails.
__device__ __forceinline__ int key_of(unsigned int bits) {
    int k = (int)(bits >> 12) - (int)KEY_BASE;
    return min(max(k, 0), NB - 1);
}

// Fenceless release/acquire (no MEMBAR.GPU / CCTL.IVALL).
__device__ __forceinline__ void red_release_add(unsigned int* p, unsigned int v) {
    asm volatile("red.release.gpu.global.add.u32 [%0], %1;"
                 :: "l"(p), "r"(v) : "memory");
}
__device__ __forceinline__ unsigned int ld_acquire(const unsigned int* p) {
    unsigned int v;
    asm volatile("ld.acquire.gpu.global.u32 %0, [%1];"
                 : "=r"(v) : "l"(p) : "memory");
    return v;
}

// ---------------------------------------------------------------------------
// One row of CE (one warp): 8 front-batched float4 loads, exp-sum, shuffle
// reduce, lane0 deposits into the counting-sort side channel (~400 L2 bins).
// ---------------------------------------------------------------------------
__device__ __forceinline__ void ce_row(const float* __restrict__ logits,
                                       const int*   __restrict__ tgt32,
                                       int row, int lane, bool is32) {
    const float*  rowp = logits + (size_t)row * C;
    const float4* r4   = (const float4*)rowp;

    float4 v[8];
    #pragma unroll
    for (int j = 0; j < 8; j++) {
        int idx = lane + 32 * j;
        v[j] = (idx < 250) ? r4[idx] : make_float4(-1e30f, -1e30f, -1e30f, -1e30f);
    }

    float xt = 0.0f;
    if (lane == 0) {
        int t = is32 ? tgt32[row] : tgt32[2 * row];
        xt = rowp[t];
    }

    float s0 = 0.f, s1 = 0.f, s2 = 0.f, s3 = 0.f;
    #pragma unroll
    for (int j = 0; j < 8; j++) {
        s0 += __expf(v[j].x); s1 += __expf(v[j].y);
        s2 += __expf(v[j].z); s3 += __expf(v[j].w);
    }
    float s = (s0 + s1) + (s2 + s3);
    #pragma unroll
    for (int o = 16; o; o >>= 1) s += __shfl_xor_sync(0xFFFFFFFFu, s, o);

    if (lane == 0) {
        float ce = __logf(s) - xt;
        unsigned int bits = __float_as_uint(ce);
        int bin = key_of(bits);
        unsigned int slot = atomicAdd(&g_hist[bin], 1u);   // returning (slot)
        if (slot < CAP) g_bucket[bin * CAP + slot] = bits;
        atomicAdd(&g_binsum[bin], ce);                     // RED, no return
    }
}

// dtype detect: odd int32 words of target buffer are zero iff int64-LE
// (targets < 1000). In-bounds for both layouts.
__device__ __forceinline__ bool detect_is32(const int* __restrict__ tgt32, int lane) {
    unsigned w1 = (unsigned)tgt32[2 * lane + 1];
    unsigned w2 = (unsigned)tgt32[2 * lane + 65];
    return __ballot_sync(0xFFFFFFFFu, (w1 | w2) != 0u) != 0u;
}

// ---------------------------------------------------------------------------
// Kernel 1: rows [0, ROWS_K1), one warp/row — proven R6 shape, smaller grid.
// ---------------------------------------------------------------------------
__global__ void __launch_bounds__(256) ce_kernel(const float* __restrict__ logits,
                                                 const int*   __restrict__ tgt32) {
    int lane = threadIdx.x & 31;
    int row  = blockIdx.x * 8 + (threadIdx.x >> 5);
    bool is32 = detect_is32(tgt32, lane);
    ce_row(logits, tgt32, row, lane, is32);
}

// ---------------------------------------------------------------------------
// Kernel 2 (single wave, 148 blocks x 1024 thr): blocks 1..147 compute the
// remaining 9408 rows (2 rows/warp) and release-signal; block 0 acquire-spins
// on them, then runs the proven selection and restores scratch invariants.
// ---------------------------------------------------------------------------
__global__ void __launch_bounds__(1024) finish_kernel(
        const float* __restrict__ logits,
        const int*   __restrict__ tgt32,
        float*       __restrict__ out) {
    int tid  = threadIdx.x;
    int lane = tid & 31, wid = tid >> 5;

    if (blockIdx.x != 0) {
        // ---- CE for the tail rows ------------------------------------------
        bool is32 = detect_is32(tgt32, lane);
        int gwarp = ((int)blockIdx.x - 1) * 32 + wid;
        int base  = ROWS_K1 + gwarp * 2;
        ce_row(logits, tgt32, base + 0, lane, is32);
        ce_row(logits, tgt32, base + 1, lane, is32);
        __syncthreads();
        if (tid == 0) red_release_add(&g_done2, 1u);
        return;
    }

    // ---- Block 0: wait for siblings (co-resident: grid == 1 wave) ---------
    if (tid == 0) {
        while (ld_acquire(&g_done2) < (unsigned)K2_CE) __nanosleep(128);
    }
    __syncthreads();

    // ---- Selection (proven R6 body) ----------------------------------------
    __shared__ unsigned int wtot[32], wsufex[32];
    __shared__ float        warp_sums[32];
    __shared__ int          sh_bin, sh_rem, sh_nB;
    __shared__ unsigned int sh_lam;
    __shared__ unsigned int sh_cand[CAP];

    const uint4*  hp = (const uint4*)g_hist;
    const float4* bp = (const float4*)g_binsum;
    uint4  h0 = hp[tid * 2],  h1 = hp[tid * 2 + 1];
    float4 b0 = bp[tid * 2],  b1 = bp[tid * 2 + 1];

    unsigned int h[8]  = {h0.x, h0.y, h0.z, h0.w, h1.x, h1.y, h1.z, h1.w};
    float        bs[8] = {b0.x, b0.y, b0.z, b0.w, b1.x, b1.y, b1.z, b1.w};

    unsigned int csum = 0;
    #pragma unroll
    for (int j = 0; j < 8; j++) csum += h[j];

    unsigned int sv = csum;
    #pragma unroll
    for (int o = 1; o < 32; o <<= 1) {
        unsigned int nb = __shfl_down_sync(0xFFFFFFFFu, sv, o);
        if (lane + o < 32) sv += nb;
    }
    if (lane == 0) wtot[wid] = sv;
    __syncthreads();
    if (wid == 0) {
        unsigned int w = wtot[lane];
        unsigned int x = w;
        #pragma unroll
        for (int o = 1; o < 32; o <<= 1) {
            unsigned int nb = __shfl_down_sync(0xFFFFFFFFu, x, o);
            if (lane + o < 32) x += nb;
        }
        wsufex[lane] = x - w;
    }
    __syncthreads();

    unsigned int sumGE = sv + wsufex[wid];
    unsigned int A     = sumGE - csum;
    if ((int)A <= K_RANK && K_RANK < (int)(A + csum)) {
        int g = (int)A;
        #pragma unroll
        for (int j = 7; j >= 0; j--) {
            int c = (int)h[j];
            if (K_RANK < g + c) {
                sh_bin = tid * 8 + j;
                sh_rem = K_RANK - g;
                sh_nB  = min(c, CAP);
                break;
            }
            g += c;
        }
    }
    __syncthreads();
    int B   = sh_bin;
    int rem = sh_rem;
    int nB  = sh_nB;

    float ksum = 0.0f;
    #pragma unroll
    for (int j = 0; j < 8; j++)
        if (tid * 8 + j > B) ksum += bs[j];

    if (tid < CAP) sh_cand[tid] = (tid < nB) ? g_bucket[B * CAP + tid] : 0u;
    __syncthreads();

    unsigned int myc = (tid < nB) ? sh_cand[tid] : 0u;
    if (tid < nB) {
        int g = 0, e = 0;
        for (int i = 0; i < nB; i++) {
            unsigned int y = sh_cand[i];
            g += (y > myc); e += (y == myc);
        }
        if (g <= rem && rem < g + e) sh_lam = myc;
    }
    __syncthreads();
    if (tid < nB && myc >= sh_lam) ksum += __uint_as_float(myc);

    #pragma unroll
    for (int o = 16; o; o >>= 1) ksum += __shfl_xor_sync(0xFFFFFFFFu, ksum, o);
    if (lane == 0) warp_sums[wid] = ksum;
    __syncthreads();
    if (wid == 0) {
        float t2 = warp_sums[lane];
        #pragma unroll
        for (int o = 16; o; o >>= 1) t2 += __shfl_xor_sync(0xFFFFFFFFu, t2, o);
        if (lane == 0) out[0] = t2 / (float)N;
    }

    // ---- Restore scratch invariants for the next graph replay -------------
    uint4*  hz = (uint4*)g_hist;
    float4* bz = (float4*)g_binsum;
    uint4  z4 = make_uint4(0u, 0u, 0u, 0u);
    float4 f4 = make_float4(0.f, 0.f, 0.f, 0.f);
    hz[tid * 2] = z4;  hz[tid * 2 + 1] = z4;
    bz[tid * 2] = f4;  bz[tid * 2 + 1] = f4;
    if (tid == 0) g_done2 = 0u;
}

// ---------------------------------------------------------------------------
extern "C" void kernel_launch(void* const* d_in, const int* in_sizes, int n_in,
                              void* d_out, int out_size) {
    const float* logits = (const float*)d_in[0];
    const int*   tgt    = (const int*)d_in[1];
    (void)in_sizes; (void)n_in; (void)out_size;

    ce_kernel<<<GRID_K1, 256>>>(logits, tgt);
    finish_kernel<<<K2_BLOCKS, 1024>>>(logits, tgt, (float*)d_out);
}

// round 13
// speedup vs baseline: 1.0063x; 1.0063x over previous
#include <cuda_runtime.h>

static constexpr int N = 32768;
static constexpr int C = 1000;
static constexpr int K_RANK = 9830;        // int(N * 0.3), 0-based descending rank
static constexpr int NB = 8192;            // histogram bins
static constexpr int CAP = 128;            // bucket capacity per bin (max obs ~70)
static constexpr unsigned int KEY_BASE = 0x40000000u >> 12;  // bits(2.0f) >> 12

// Kernel-2 geometry: ONE guaranteed-resident wave.
// __launch_bounds__(256, 5) caps regs at 51 -> 5 blocks/SM x 148 SMs = 740.
static constexpr int FINISH_GRID = 740;
static constexpr int K2_CE       = FINISH_GRID - 1;     // 739 CE blocks
static constexpr int ROWS_K2     = K2_CE * 8;           // 5912 rows (1/warp)
static constexpr int ROWS_K1     = N - ROWS_K2;         // 26856
static constexpr int GRID_K1     = ROWS_K1 / 8;         // 3357

__device__ unsigned int g_hist[NB];            // counts / bucket slot counters
__device__ float        g_binsum[NB];          // per-bin CE sums
__device__ unsigned int g_bucket[NB * CAP];    // CE bit patterns by bin
__device__ unsigned int g_done2;               // kernel-2 CE completion counter

// key: 2 exponent bits + 11 mantissa bits over [2.0, 32.0), clamped tails.
__device__ __forceinline__ int key_of(unsigned int bits) {
    int k = (int)(bits >> 12) - (int)KEY_BASE;
    return min(max(k, 0), NB - 1);
}

// Fenceless release/acquire (no MEMBAR.GPU / CCTL.IVALL).
__device__ __forceinline__ void red_release_add(unsigned int* p, unsigned int v) {
    asm volatile("red.release.gpu.global.add.u32 [%0], %1;"
                 :: "l"(p), "r"(v) : "memory");
}
__device__ __forceinline__ unsigned int ld_acquire(const unsigned int* p) {
    unsigned int v;
    asm volatile("ld.acquire.gpu.global.u32 %0, [%1];"
                 : "=r"(v) : "l"(p) : "memory");
    return v;
}

// ---------------------------------------------------------------------------
// One row of CE (one warp): 8 front-batched float4 loads, exp-sum, shuffle
// reduce; lane0 deposits into the counting-sort side channel (~400 L2 bins).
// ---------------------------------------------------------------------------
__device__ __forceinline__ void ce_row(const float* __restrict__ logits,
                                       const int*   __restrict__ tgt32,
                                       int row, int lane, bool is32) {
    const float*  rowp = logits + (size_t)row * C;
    const float4* r4   = (const float4*)rowp;

    float4 v[8];
    #pragma unroll
    for (int j = 0; j < 8; j++) {
        int idx = lane + 32 * j;
        v[j] = (idx < 250) ? r4[idx] : make_float4(-1e30f, -1e30f, -1e30f, -1e30f);
    }

    float xt = 0.0f;
    if (lane == 0) {
        int t = is32 ? tgt32[row] : tgt32[2 * row];
        xt = rowp[t];
    }

    float s0 = 0.f, s1 = 0.f, s2 = 0.f, s3 = 0.f;
    #pragma unroll
    for (int j = 0; j < 8; j++) {
        s0 += __expf(v[j].x); s1 += __expf(v[j].y);
        s2 += __expf(v[j].z); s3 += __expf(v[j].w);
    }
    float s = (s0 + s1) + (s2 + s3);
    #pragma unroll
    for (int o = 16; o; o >>= 1) s += __shfl_xor_sync(0xFFFFFFFFu, s, o);

    if (lane == 0) {
        float ce = __logf(s) - xt;
        unsigned int bits = __float_as_uint(ce);
        int bin = key_of(bits);
        unsigned int slot = atomicAdd(&g_hist[bin], 1u);   // returning (slot)
        if (slot < CAP) g_bucket[bin * CAP + slot] = bits;
        atomicAdd(&g_binsum[bin], ce);                     // RED, no return
    }
}

// dtype detect: odd int32 words of target buffer are zero iff int64-LE
// (targets < 1000). In-bounds for both layouts.
__device__ __forceinline__ bool detect_is32(const int* __restrict__ tgt32, int lane) {
    unsigned w1 = (unsigned)tgt32[2 * lane + 1];
    unsigned w2 = (unsigned)tgt32[2 * lane + 65];
    return __ballot_sync(0xFFFFFFFFu, (w1 | w2) != 0u) != 0u;
}

// ---------------------------------------------------------------------------
// Kernel 1: rows [0, ROWS_K1), one warp/row — proven R6 shape, smaller grid.
// ---------------------------------------------------------------------------
__global__ void __launch_bounds__(256) ce_kernel(const float* __restrict__ logits,
                                                 const int*   __restrict__ tgt32) {
    int lane = threadIdx.x & 31;
    int row  = blockIdx.x * 8 + (threadIdx.x >> 5);
    bool is32 = detect_is32(tgt32, lane);
    ce_row(logits, tgt32, row, lane, is32);
}

// ---------------------------------------------------------------------------
// Kernel 2: 740 blocks x 256 thr, ONE resident wave (launch_bounds-enforced).
// Blocks 1..739: last 5912 rows of CE (proven 1-row/warp shape), then one
// fenceless release. Block 0: acquire-spin, then register-light selection
// (R9-proven body), output, and scratch-invariant restore for graph replay.
// ---------------------------------------------------------------------------
__global__ void __launch_bounds__(256, 5) finish_kernel(
        const float* __restrict__ logits,
        const int*   __restrict__ tgt32,
        float*       __restrict__ out) {
    int tid  = threadIdx.x;
    int lane = tid & 31, wid = tid >> 5;

    if (blockIdx.x != 0) {
        bool is32 = detect_is32(tgt32, lane);
        int row = ROWS_K1 + ((int)blockIdx.x - 1) * 8 + wid;
        ce_row(logits, tgt32, row, lane, is32);
        __syncthreads();
        if (tid == 0) red_release_add(&g_done2, 1u);
        return;
    }

    // ---- Block 0: wait for the 739 co-resident CE siblings -----------------
    __shared__ unsigned int wtot[8], wsufex[8];
    __shared__ float        warp_sums[8];
    __shared__ int          sh_bin, sh_rem, sh_nB;
    __shared__ unsigned int sh_lam;
    __shared__ unsigned int sh_cand[CAP];

    if (tid == 0) {
        while (ld_acquire(&g_done2) < (unsigned)K2_CE) __nanosleep(128);
    }
    __syncthreads();

    // ---- Pass 1: counts (32 contiguous bins/thread, 8x LDG.128) -----------
    const uint4* hp = (const uint4*)g_hist;
    unsigned int csum = 0;
    #pragma unroll
    for (int j = 0; j < 8; j++) {
        uint4 q = hp[tid * 8 + j];
        csum += q.x + q.y + q.z + q.w;
    }

    unsigned int sv = csum;
    #pragma unroll
    for (int o = 1; o < 32; o <<= 1) {
        unsigned int nb = __shfl_down_sync(0xFFFFFFFFu, sv, o);
        if (lane + o < 32) sv += nb;
    }
    if (lane == 0) wtot[wid] = sv;
    __syncthreads();
    if (wid == 0 && lane < 8) {
        unsigned int w = wtot[lane];
        unsigned int x = w;
        #pragma unroll
        for (int o = 1; o < 8; o <<= 1) {
            unsigned int nb = __shfl_down_sync(0x000000FFu, x, o);
            if (lane + o < 8) x += nb;
        }
        wsufex[lane] = x - w;
    }
    __syncthreads();

    unsigned int sumGE = sv + wsufex[wid];   // # in bins >= 32*tid
    unsigned int A     = sumGE - csum;       // # in bins >= 32*(tid+1)
    if ((int)A <= K_RANK && K_RANK < (int)(A + csum)) {
        int g = (int)A;                      // owner re-walks its 32 bins (hot)
        for (int j = 31; j >= 0; j--) {
            int c = (int)g_hist[tid * 32 + j];
            if (K_RANK < g + c) {
                sh_bin = tid * 32 + j;
                sh_rem = K_RANK - g;
                sh_nB  = min(c, CAP);
                break;
            }
            g += c;
        }
    }
    __syncthreads();
    int B   = sh_bin;
    int rem = sh_rem;
    int nB  = sh_nB;

    // ---- Pass 2: kept-sum over bins > B ------------------------------------
    const float4* bp = (const float4*)g_binsum;
    float ksum = 0.0f;
    #pragma unroll
    for (int j = 0; j < 8; j++) {
        float4 f = bp[tid * 8 + j];
        int b0 = tid * 32 + j * 4;
        if (b0 + 0 > B) ksum += f.x;
        if (b0 + 1 > B) ksum += f.y;
        if (b0 + 2 > B) ksum += f.z;
        if (b0 + 3 > B) ksum += f.w;
    }

    // ---- Bucket-B candidates: stage to smem, exact tie-safe rank ----------
    if (tid < CAP) sh_cand[tid] = (tid < nB) ? g_bucket[B * CAP + tid] : 0u;
    __syncthreads();

    unsigned int myc = (tid < nB) ? sh_cand[tid] : 0u;
    if (tid < nB) {
        int g = 0, e = 0;
        for (int i = 0; i < nB; i++) {
            unsigned int y = sh_cand[i];
            g += (y > myc); e += (y == myc);
        }
        if (g <= rem && rem < g + e) sh_lam = myc;
    }
    __syncthreads();
    if (tid < nB && myc >= sh_lam) ksum += __uint_as_float(myc);

    // ---- Block reduce + output ---------------------------------------------
    #pragma unroll
    for (int o = 16; o; o >>= 1) ksum += __shfl_xor_sync(0xFFFFFFFFu, ksum, o);
    if (lane == 0) warp_sums[wid] = ksum;
    __syncthreads();
    if (tid == 0) {
        float t2 = 0.0f;
        #pragma unroll
        for (int i = 0; i < 8; i++) t2 += warp_sums[i];
        out[0] = t2 / (float)N;
    }

    // ---- Restore scratch invariants (fire-and-forget wide stores) ---------
    uint4*  hz = (uint4*)g_hist;
    float4* bz = (float4*)g_binsum;
    uint4  z4 = make_uint4(0u, 0u, 0u, 0u);
    float4 f4 = make_float4(0.f, 0.f, 0.f, 0.f);
    #pragma unroll
    for (int j = 0; j < 8; j++) {
        hz[tid * 8 + j] = z4;
        bz[tid * 8 + j] = f4;
    }
    if (tid == 0) g_done2 = 0u;
}

// ---------------------------------------------------------------------------
extern "C" void kernel_launch(void* const* d_in, const int* in_sizes, int n_in,
                              void* d_out, int out_size) {
    const float* logits = (const float*)d_in[0];
    const int*   tgt    = (const int*)d_in[1];
    (void)in_sizes; (void)n_in; (void)out_size;

    ce_kernel<<<GRID_K1, 256>>>(logits, tgt);
    finish_kernel<<<FINISH_GRID, 256>>>(logits, tgt, (float*)d_out);
}

// round 14
// speedup vs baseline: 1.1000x; 1.0931x over previous
#include <cuda_runtime.h>

static constexpr int N = 32768;
static constexpr int C = 1000;
static constexpr int K_RANK = 9830;        // int(N * 0.3), 0-based descending rank
static constexpr int NB = 8192;            // histogram bins
static constexpr int CAP = 128;            // bucket capacity per bin (max obs ~70)
static constexpr unsigned int KEY_BASE = 0x40000000u >> 12;  // bits(2.0f) >> 12

// Persistent CE grid: 3 blocks/SM x 148 SMs = 444, one resident wave.
static constexpr int CE_GRID  = 444;
static constexpr int CE_WARPS = CE_GRID * 8;   // 3552 grid-striding warps

__device__ unsigned int g_hist[NB];            // counts / bucket slot counters
__device__ float        g_binsum[NB];          // per-bin CE sums
__device__ unsigned int g_bucket[NB * CAP];    // CE bit patterns by bin

// key: 2 exponent bits + 11 mantissa bits over [2.0, 32.0), clamped tails.
// CE = logsumexp - x_t with logits ~ N(0,1): essentially always in [2, 16).
__device__ __forceinline__ int key_of(unsigned int bits) {
    int k = (int)(bits >> 12) - (int)KEY_BASE;
    return min(max(k, 0), NB - 1);
}

// Front-batched row load: 8 predicated float4 (MLP=8 per row).
__device__ __forceinline__ void load_row(float4* v, const float4* r4, int lane) {
    #pragma unroll
    for (int j = 0; j < 8; j++) {
        int idx = lane + 32 * j;
        v[j] = (idx < 250) ? r4[idx] : make_float4(-1e30f, -1e30f, -1e30f, -1e30f);
    }
}

// Compute exp-sum of a loaded row, reduce, deposit CE into the side channel.
__device__ __forceinline__ void finish_row(const float4* v,
                                           const float* __restrict__ rowp,
                                           const int*   __restrict__ tgt32,
                                           int row, int lane, bool is32) {
    float xt = 0.0f;
    if (lane == 0) {
        int t = is32 ? tgt32[row] : tgt32[2 * row];
        xt = rowp[t];
    }

    float s0 = 0.f, s1 = 0.f, s2 = 0.f, s3 = 0.f;
    #pragma unroll
    for (int j = 0; j < 8; j++) {
        s0 += __expf(v[j].x); s1 += __expf(v[j].y);
        s2 += __expf(v[j].z); s3 += __expf(v[j].w);
    }
    float s = (s0 + s1) + (s2 + s3);
    #pragma unroll
    for (int o = 16; o; o >>= 1) s += __shfl_xor_sync(0xFFFFFFFFu, s, o);

    if (lane == 0) {
        float ce = __logf(s) - xt;
        unsigned int bits = __float_as_uint(ce);
        int bin = key_of(bits);
        unsigned int slot = atomicAdd(&g_hist[bin], 1u);   // returning (slot)
        if (slot < CAP) g_bucket[bin * CAP + slot] = bits;
        atomicAdd(&g_binsum[bin], ce);                     // RED, no return
    }
}

// ---------------------------------------------------------------------------
// Kernel 1: persistent, software-pipelined CE. Each warp grid-strides over
// ~9 rows; the NEXT row's 8 float4 are prefetched into registers before the
// CURRENT row's exp-sum, keeping the memory pipe full across row boundaries
// and eliminating wave-transition drains entirely (single resident wave).
// ---------------------------------------------------------------------------
__global__ void __launch_bounds__(256, 3) ce_kernel(
        const float* __restrict__ logits,
        const int*   __restrict__ tgt32) {
    int lane = threadIdx.x & 31;
    int wid  = threadIdx.x >> 5;

    // dtype detect: odd int32 words of target buffer are zero iff int64-LE
    // (targets < 1000). In-bounds for both layouts.
    unsigned dw1 = (unsigned)tgt32[2 * lane + 1];
    unsigned dw2 = (unsigned)tgt32[2 * lane + 65];
    bool is32 = __ballot_sync(0xFFFFFFFFu, (dw1 | dw2) != 0u) != 0u;

    int row = blockIdx.x * 8 + wid;               // first row for this warp

    float4 cur[8];
    load_row(cur, (const float4*)(logits + (size_t)row * C), lane);

    while (true) {
        int nrow = row + CE_WARPS;
        float4 nxt[8];
        bool has_next = (nrow < N);
        if (has_next)
            load_row(nxt, (const float4*)(logits + (size_t)nrow * C), lane);

        finish_row(cur, logits + (size_t)row * C, tgt32, row, lane, is32);

        if (!has_next) break;
        #pragma unroll
        for (int j = 0; j < 8; j++) cur[j] = nxt[j];
        row = nrow;
    }
}

// ---------------------------------------------------------------------------
// Kernel 2: exact R6 selection (proven). Single block, 1024 threads, inputs
// L2-hot. Suffix-scan hist -> threshold bin + residual rank; kept-sum from
// binsum; exact tie-safe lambda from bucket B (smem); mean; re-zero scratch.
// ---------------------------------------------------------------------------
__global__ void __launch_bounds__(1024) select_kernel(float* __restrict__ out) {
    __shared__ unsigned int wtot[32], wsufex[32];
    __shared__ float        warp_sums[32];
    __shared__ int          sh_bin, sh_rem, sh_nB;
    __shared__ unsigned int sh_lam;
    __shared__ unsigned int sh_cand[CAP];

    int tid  = threadIdx.x;
    int lane = tid & 31, wid = tid >> 5;

    // Front-batched independent global loads: 8 hist + 8 binsum per thread.
    const uint4*  hp = (const uint4*)g_hist;
    const float4* bp = (const float4*)g_binsum;
    uint4  h0 = hp[tid * 2],  h1 = hp[tid * 2 + 1];
    float4 b0 = bp[tid * 2],  b1 = bp[tid * 2 + 1];

    unsigned int h[8]  = {h0.x, h0.y, h0.z, h0.w, h1.x, h1.y, h1.z, h1.w};
    float        bs[8] = {b0.x, b0.y, b0.z, b0.w, b1.x, b1.y, b1.z, b1.w};

    unsigned int csum = 0;
    #pragma unroll
    for (int j = 0; j < 8; j++) csum += h[j];

    // Two-level inclusive suffix scan over per-thread chunk sums.
    unsigned int sv = csum;
    #pragma unroll
    for (int o = 1; o < 32; o <<= 1) {
        unsigned int nb = __shfl_down_sync(0xFFFFFFFFu, sv, o);
        if (lane + o < 32) sv += nb;
    }
    if (lane == 0) wtot[wid] = sv;
    __syncthreads();
    if (wid == 0) {
        unsigned int w = wtot[lane];
        unsigned int x = w;
        #pragma unroll
        for (int o = 1; o < 32; o <<= 1) {
            unsigned int nb = __shfl_down_sync(0xFFFFFFFFu, x, o);
            if (lane + o < 32) x += nb;
        }
        wsufex[lane] = x - w;
    }
    __syncthreads();

    unsigned int sumGE = sv + wsufex[wid];   // # in bins >= 8*tid
    unsigned int A     = sumGE - csum;       // # in bins >= 8*(tid+1)
    if ((int)A <= K_RANK && K_RANK < (int)(A + csum)) {
        int g = (int)A;
        #pragma unroll
        for (int j = 7; j >= 0; j--) {
            int c = (int)h[j];
            if (K_RANK < g + c) {
                sh_bin = tid * 8 + j;
                sh_rem = K_RANK - g;
                sh_nB  = min(c, CAP);   // hist[B] already in a register here
                break;
            }
            g += c;
        }
    }
    __syncthreads();
    int B   = sh_bin;
    int rem = sh_rem;
    int nB  = sh_nB;

    // Sum of all bins strictly above B (values already in registers).
    float ksum = 0.0f;
    #pragma unroll
    for (int j = 0; j < 8; j++)
        if (tid * 8 + j > B) ksum += bs[j];

    // Stage bucket-B candidates into shared memory (one parallel L2 round).
    if (tid < CAP) sh_cand[tid] = (tid < nB) ? g_bucket[B * CAP + tid] : 0u;
    __syncthreads();

    // Exact tie-safe lambda among candidates; smem broadcast loads only.
    unsigned int myc = (tid < nB) ? sh_cand[tid] : 0u;
    if (tid < nB) {
        int g = 0, e = 0;
        for (int i = 0; i < nB; i++) {
            unsigned int y = sh_cand[i];
            g += (y > myc); e += (y == myc);
        }
        if (g <= rem && rem < g + e) sh_lam = myc;
    }
    __syncthreads();
    if (tid < nB && myc >= sh_lam) ksum += __uint_as_float(myc);

    // Block reduce and write output.
    #pragma unroll
    for (int o = 16; o; o >>= 1) ksum += __shfl_xor_sync(0xFFFFFFFFu, ksum, o);
    if (lane == 0) warp_sums[wid] = ksum;
    __syncthreads();
    if (wid == 0) {
        float t2 = warp_sums[lane];
        #pragma unroll
        for (int o = 16; o; o >>= 1) t2 += __shfl_xor_sync(0xFFFFFFFFu, t2, o);
        if (lane == 0) out[0] = t2 / (float)N;
    }

    // Restore scratch invariants for the next graph replay (vector stores).
    uint4*  hz = (uint4*)g_hist;
    float4* bz = (float4*)g_binsum;
    uint4  z4 = make_uint4(0u, 0u, 0u, 0u);
    float4 f4 = make_float4(0.f, 0.f, 0.f, 0.f);
    hz[tid * 2] = z4;  hz[tid * 2 + 1] = z4;
    bz[tid * 2] = f4;  bz[tid * 2 + 1] = f4;
}

// ---------------------------------------------------------------------------
extern "C" void kernel_launch(void* const* d_in, const int* in_sizes, int n_in,
                              void* d_out, int out_size) {
    const float* logits = (const float*)d_in[0];
    const int*   tgt    = (const int*)d_in[1];
    (void)in_sizes; (void)n_in; (void)out_size;

    ce_kernel<<<CE_GRID, 256>>>(logits, tgt);
    select_kernel<<<1, 1024>>>((float*)d_out);
}

// round 15
// speedup vs baseline: 1.1302x; 1.0275x over previous
#include <cuda_runtime.h>

static constexpr int N = 32768;
static constexpr int C = 1000;
static constexpr int K_RANK = 9830;        // int(N * 0.3), 0-based descending rank
static constexpr int NB = 8192;            // histogram bins
static constexpr int CAP = 128;            // bucket capacity per bin (max obs ~70)
static constexpr unsigned int KEY_BASE = 0x40000000u >> 12;  // bits(2.0f) >> 12

__device__ unsigned int g_hist[NB];            // counts / bucket slot counters
__device__ float        g_binsum[NB];          // per-bin CE sums
__device__ unsigned int g_bucket[NB * CAP];    // CE bit patterns by bin

// key: 2 exponent bits + 11 mantissa bits over [2.0, 32.0), clamped tails.
// CE = logsumexp - x_t with logits ~ N(0,1): essentially always in [2, 16).
__device__ __forceinline__ int key_of(unsigned int bits) {
    int k = (int)(bits >> 12) - (int)KEY_BASE;
    return min(max(k, 0), NB - 1);
}

// Streaming float4 load (evict-first in L2; logits are read exactly once).
__device__ __forceinline__ float4 ldcs4(const float4* p) {
    return __ldcs(p);
}

// ---------------------------------------------------------------------------
// Kernel 1: per-row CE = log(sum exp(x)) - x[target]; one warp per row.
// Exact R6 structure (proven 6.4 TB/s); logits loads use evict-first hint so
// the one-shot stream doesn't evict the hot histogram/bucket L2 lines.
// ---------------------------------------------------------------------------
__global__ void __launch_bounds__(256) ce_kernel(const float* __restrict__ logits,
                                                 const int*   __restrict__ tgt32) {
    int lane = threadIdx.x & 31;
    int row  = blockIdx.x * 8 + (threadIdx.x >> 5);

    const float*  rowp = logits + (size_t)row * C;
    const float4* r4   = (const float4*)rowp;

    // Front-batch all loads (MLP=8). OOB lanes: -1e30 -> exp underflows to 0.
    float4 v[8];
    #pragma unroll
    for (int j = 0; j < 8; j++) {
        int idx = lane + 32 * j;
        v[j] = (idx < 250) ? ldcs4(&r4[idx]) : make_float4(-1e30f, -1e30f, -1e30f, -1e30f);
    }

    // dtype detect: odd int32 words of target buffer are zero iff int64-LE
    // (targets < 1000). In-bounds for both layouts.
    unsigned w1 = (unsigned)tgt32[2 * lane + 1];
    unsigned w2 = (unsigned)tgt32[2 * lane + 65];
    bool is32 = __ballot_sync(0xFFFFFFFFu, (w1 | w2) != 0u) != 0u;

    float xt = 0.0f;
    if (lane == 0) {
        int t = is32 ? tgt32[row] : tgt32[2 * row];
        xt = rowp[t];
    }

    float s0 = 0.f, s1 = 0.f, s2 = 0.f, s3 = 0.f;
    #pragma unroll
    for (int j = 0; j < 8; j++) {
        s0 += __expf(v[j].x); s1 += __expf(v[j].y);
        s2 += __expf(v[j].z); s3 += __expf(v[j].w);
    }
    float s = (s0 + s1) + (s2 + s3);
    #pragma unroll
    for (int o = 16; o; o >>= 1) s += __shfl_xor_sync(0xFFFFFFFFu, s, o);

    if (lane == 0) {
        float ce = __logf(s) - xt;
        unsigned int bits = __float_as_uint(ce);
        int bin = key_of(bits);
        unsigned int slot = atomicAdd(&g_hist[bin], 1u);   // returning (slot)
        if (slot < CAP) g_bucket[bin * CAP + slot] = bits;
        atomicAdd(&g_binsum[bin], ce);                     // RED, no return
    }
}

// ---------------------------------------------------------------------------
// Kernel 2: 256-thread selection (R9-proven tail body) — block-shape probe
// of the grid-1 kernel floor (all prior grid-1 kernels used 1024 threads).
// 32 contiguous bins/thread, two passes over L2-hot hist/binsum, exact
// tie-safe lambda from bucket B in smem; restores scratch invariants.
// ---------------------------------------------------------------------------
__global__ void __launch_bounds__(256) select_kernel(float* __restrict__ out) {
    __shared__ unsigned int wtot[8], wsufex[8];
    __shared__ float        warp_sums[8];
    __shared__ int          sh_bin, sh_rem, sh_nB;
    __shared__ unsigned int sh_lam;
    __shared__ unsigned int sh_cand[CAP];

    int tid  = threadIdx.x;
    int lane = tid & 31, wid = tid >> 5;

    // ---- Pass 1: counts (32 contiguous bins/thread, 8x LDG.128) -----------
    const uint4* hp = (const uint4*)g_hist;
    unsigned int csum = 0;
    #pragma unroll
    for (int j = 0; j < 8; j++) {
        uint4 q = hp[tid * 8 + j];
        csum += q.x + q.y + q.z + q.w;
    }

    // Two-level inclusive suffix scan (256 threads, 8 warps).
    unsigned int sv = csum;
    #pragma unroll
    for (int o = 1; o < 32; o <<= 1) {
        unsigned int nb = __shfl_down_sync(0xFFFFFFFFu, sv, o);
        if (lane + o < 32) sv += nb;
    }
    if (lane == 0) wtot[wid] = sv;
    __syncthreads();
    if (wid == 0 && lane < 8) {
        unsigned int w = wtot[lane];
        unsigned int x = w;
        #pragma unroll
        for (int o = 1; o < 8; o <<= 1) {
            unsigned int nb = __shfl_down_sync(0x000000FFu, x, o);
            if (lane + o < 8) x += nb;
        }
        wsufex[lane] = x - w;
    }
    __syncthreads();

    unsigned int sumGE = sv + wsufex[wid];   // # in bins >= 32*tid
    unsigned int A     = sumGE - csum;       // # in bins >= 32*(tid+1)
    if ((int)A <= K_RANK && K_RANK < (int)(A + csum)) {
        int g = (int)A;                      // owner re-walks its 32 bins (hot)
        for (int j = 31; j >= 0; j--) {
            int c = (int)g_hist[tid * 32 + j];
            if (K_RANK < g + c) {
                sh_bin = tid * 32 + j;
                sh_rem = K_RANK - g;
                sh_nB  = min(c, CAP);
                break;
            }
            g += c;
        }
    }
    __syncthreads();
    int B   = sh_bin;
    int rem = sh_rem;
    int nB  = sh_nB;

    // ---- Pass 2: kept-sum over bins > B ------------------------------------
    const float4* bp = (const float4*)g_binsum;
    float ksum = 0.0f;
    #pragma unroll
    for (int j = 0; j < 8; j++) {
        float4 f = bp[tid * 8 + j];
        int b0 = tid * 32 + j * 4;
        if (b0 + 0 > B) ksum += f.x;
        if (b0 + 1 > B) ksum += f.y;
        if (b0 + 2 > B) ksum += f.z;
        if (b0 + 3 > B) ksum += f.w;
    }

    // ---- Bucket-B candidates: stage to smem, exact tie-safe rank ----------
    if (tid < CAP) sh_cand[tid] = (tid < nB) ? g_bucket[B * CAP + tid] : 0u;
    __syncthreads();

    unsigned int myc = (tid < nB) ? sh_cand[tid] : 0u;
    if (tid < nB) {
        int g = 0, e = 0;
        for (int i = 0; i < nB; i++) {
            unsigned int y = sh_cand[i];
            g += (y > myc); e += (y == myc);
        }
        if (g <= rem && rem < g + e) sh_lam = myc;
    }
    __syncthreads();
    if (tid < nB && myc >= sh_lam) ksum += __uint_as_float(myc);

    // ---- Block reduce + output ---------------------------------------------
    #pragma unroll
    for (int o = 16; o; o >>= 1) ksum += __shfl_xor_sync(0xFFFFFFFFu, ksum, o);
    if (lane == 0) warp_sums[wid] = ksum;
    __syncthreads();
    if (tid == 0) {
        float t2 = 0.0f;
        #pragma unroll
        for (int i = 0; i < 8; i++) t2 += warp_sums[i];
        out[0] = t2 / (float)N;
    }

    // ---- Restore scratch invariants (fire-and-forget wide stores) ---------
    uint4*  hz = (uint4*)g_hist;
    float4* bz = (float4*)g_binsum;
    uint4  z4 = make_uint4(0u, 0u, 0u, 0u);
    float4 f4 = make_float4(0.f, 0.f, 0.f, 0.f);
    #pragma unroll
    for (int j = 0; j < 8; j++) {
        hz[tid * 8 + j] = z4;
        bz[tid * 8 + j] = f4;
    }
}

// ---------------------------------------------------------------------------
extern "C" void kernel_launch(void* const* d_in, const int* in_sizes, int n_in,
                              void* d_out, int out_size) {
    const float* logits = (const float*)d_in[0];
    const int*   tgt    = (const int*)d_in[1];
    (void)in_sizes; (void)n_in; (void)out_size;

    ce_kernel<<<N / 8, 256>>>(logits, tgt);
    select_kernel<<<1, 256>>>((float*)d_out);
}

// round 16
// speedup vs baseline: 1.1695x; 1.0347x over previous
#include <cuda_runtime.h>

static constexpr int N = 32768;
static constexpr int C = 1000;
static constexpr int K_RANK = 9830;        // int(N * 0.3), 0-based descending rank
static constexpr int NB = 8192;            // histogram bins
static constexpr int CAP = 128;            // bucket capacity per bin (max obs ~70)
static constexpr unsigned int KEY_BASE = 0x40000000u >> 12;  // bits(2.0f) >> 12

__device__ unsigned int g_hist[NB];            // counts / bucket slot counters
__device__ float        g_binsum[NB];          // per-bin CE sums
__device__ unsigned int g_bucket[NB * CAP];    // CE bit patterns by bin

// key: 2 exponent bits + 11 mantissa bits over [2.0, 32.0), clamped tails.
// CE = logsumexp - x_t with logits ~ N(0,1): essentially always in [2, 16).
__device__ __forceinline__ int key_of(unsigned int bits) {
    int k = (int)(bits >> 12) - (int)KEY_BASE;
    return min(max(k, 0), NB - 1);
}

// ---------------------------------------------------------------------------
// Kernel 1: per-row CE = log(sum exp(x)) - x[target]; one warp per row.
// Side channel: counting-sort bucket (bits) + per-bin float sum. All atomics
// are one-per-warp, L2-resident, hidden under the HBM-bound mainloop.
// This exact shape measured 6.4 TB/s; every variant tried regressed it.
// ---------------------------------------------------------------------------
__global__ void __launch_bounds__(256) ce_kernel(const float* __restrict__ logits,
                                                 const int*   __restrict__ tgt32) {
    int lane = threadIdx.x & 31;
    int row  = blockIdx.x * 8 + (threadIdx.x >> 5);

    const float*  rowp = logits + (size_t)row * C;
    const float4* r4   = (const float4*)rowp;

    // Front-batch all loads (MLP=8). OOB lanes: -1e30 -> exp underflows to 0.
    float4 v[8];
    #pragma unroll
    for (int j = 0; j < 8; j++) {
        int idx = lane + 32 * j;
        v[j] = (idx < 250) ? r4[idx] : make_float4(-1e30f, -1e30f, -1e30f, -1e30f);
    }

    // dtype detect: odd int32 words of target buffer are zero iff int64-LE
    // (targets < 1000). In-bounds for both layouts.
    unsigned w1 = (unsigned)tgt32[2 * lane + 1];
    unsigned w2 = (unsigned)tgt32[2 * lane + 65];
    bool is32 = __ballot_sync(0xFFFFFFFFu, (w1 | w2) != 0u) != 0u;

    float xt = 0.0f;
    if (lane == 0) {
        int t = is32 ? tgt32[row] : tgt32[2 * row];
        xt = rowp[t];
    }

    float s0 = 0.f, s1 = 0.f, s2 = 0.f, s3 = 0.f;
    #pragma unroll
    for (int j = 0; j < 8; j++) {
        s0 += __expf(v[j].x); s1 += __expf(v[j].y);
        s2 += __expf(v[j].z); s3 += __expf(v[j].w);
    }
    float s = (s0 + s1) + (s2 + s3);
    #pragma unroll
    for (int o = 16; o; o >>= 1) s += __shfl_xor_sync(0xFFFFFFFFu, s, o);

    if (lane == 0) {
        float ce = __logf(s) - xt;
        unsigned int bits = __float_as_uint(ce);
        int bin = key_of(bits);
        unsigned int slot = atomicAdd(&g_hist[bin], 1u);   // returning (slot)
        if (slot < CAP) g_bucket[bin * CAP + slot] = bits;
        atomicAdd(&g_binsum[bin], ce);                     // RED, no return
    }

#if __CUDA_ARCH__ >= 900
    cudaTriggerProgrammaticLaunchCompletion();
#endif
}

// ---------------------------------------------------------------------------
// Kernel 2: single block, 1024 threads, inputs L2-hot (64 KB + one bucket
// row). All global latencies overlapped at the top; candidate rank runs out
// of shared memory. Measured at the grid-1 kernel floor (~7.2 us) — the body
// is not the binding constraint. Restores scratch invariants for replay.
// ---------------------------------------------------------------------------
__global__ void __launch_bounds__(1024) select_kernel(float* __restrict__ out) {
    __shared__ unsigned int wtot[32], wsufex[32];
    __shared__ float        warp_sums[32];
    __shared__ int          sh_bin, sh_rem, sh_nB;
    __shared__ unsigned int sh_lam;
    __shared__ unsigned int sh_cand[CAP];

#if __CUDA_ARCH__ >= 900
    cudaGridDependencySynchronize();
#endif

    int tid  = threadIdx.x;
    int lane = tid & 31, wid = tid >> 5;

    // Front-batched independent global loads: 8 hist + 8 binsum per thread.
    const uint4*  hp = (const uint4*)g_hist;
    const float4* bp = (const float4*)g_binsum;
    uint4  h0 = hp[tid * 2],  h1 = hp[tid * 2 + 1];
    float4 b0 = bp[tid * 2],  b1 = bp[tid * 2 + 1];

    unsigned int h[8]  = {h0.x, h0.y, h0.z, h0.w, h1.x, h1.y, h1.z, h1.w};
    float        bs[8] = {b0.x, b0.y, b0.z, b0.w, b1.x, b1.y, b1.z, b1.w};

    unsigned int csum = 0;
    #pragma unroll
    for (int j = 0; j < 8; j++) csum += h[j];

    // Two-level inclusive suffix scan over per-thread chunk sums.
    unsigned int sv = csum;
    #pragma unroll
    for (int o = 1; o < 32; o <<= 1) {
        unsigned int nb = __shfl_down_sync(0xFFFFFFFFu, sv, o);
        if (lane + o < 32) sv += nb;
    }
    if (lane == 0) wtot[wid] = sv;
    __syncthreads();
    if (wid == 0) {
        unsigned int w = wtot[lane];
        unsigned int x = w;
        #pragma unroll
        for (int o = 1; o < 32; o <<= 1) {
            unsigned int nb = __shfl_down_sync(0xFFFFFFFFu, x, o);
            if (lane + o < 32) x += nb;
        }
        wsufex[lane] = x - w;
    }
    __syncthreads();

    unsigned int sumGE = sv + wsufex[wid];   // # in bins >= 8*tid
    unsigned int A     = sumGE - csum;       // # in bins >= 8*(tid+1)
    if ((int)A <= K_RANK && K_RANK < (int)(A + csum)) {
        int g = (int)A;
        #pragma unroll
        for (int j = 7; j >= 0; j--) {
            int c = (int)h[j];
            if (K_RANK < g + c) {
                sh_bin = tid * 8 + j;
                sh_rem = K_RANK - g;
                sh_nB  = min(c, CAP);   // hist[B] already in a register here
                break;
            }
            g += c;
        }
    }
    __syncthreads();
    int B   = sh_bin;
    int rem = sh_rem;
    int nB  = sh_nB;

    // Sum of all bins strictly above B (values already in registers).
    float ksum = 0.0f;
    #pragma unroll
    for (int j = 0; j < 8; j++)
        if (tid * 8 + j > B) ksum += bs[j];

    // Stage bucket-B candidates into shared memory (one parallel L2 round).
    if (tid < CAP) sh_cand[tid] = (tid < nB) ? g_bucket[B * CAP + tid] : 0u;
    __syncthreads();

    // Exact tie-safe lambda among candidates; smem broadcast loads only.
    unsigned int myc = (tid < nB) ? sh_cand[tid] : 0u;
    if (tid < nB) {
        int g = 0, e = 0;
        for (int i = 0; i < nB; i++) {
            unsigned int y = sh_cand[i];
            g += (y > myc); e += (y == myc);
        }
        if (g <= rem && rem < g + e) sh_lam = myc;
    }
    __syncthreads();
    if (tid < nB && myc >= sh_lam) ksum += __uint_as_float(myc);

    // Block reduce and write output.
    #pragma unroll
    for (int o = 16; o; o >>= 1) ksum += __shfl_xor_sync(0xFFFFFFFFu, ksum, o);
    if (lane == 0) warp_sums[wid] = ksum;
    __syncthreads();
    if (wid == 0) {
        float t2 = warp_sums[lane];
        #pragma unroll
        for (int o = 16; o; o >>= 1) t2 += __shfl_xor_sync(0xFFFFFFFFu, t2, o);
        if (lane == 0) out[0] = t2 / (float)N;
    }

    // Restore scratch invariants for the next graph replay (vector stores).
    uint4*  hz = (uint4*)g_hist;
    float4* bz = (float4*)g_binsum;
    uint4  z4 = make_uint4(0u, 0u, 0u, 0u);
    float4 f4 = make_float4(0.f, 0.f, 0.f, 0.f);
    hz[tid * 2] = z4;  hz[tid * 2 + 1] = z4;
    bz[tid * 2] = f4;  bz[tid * 2 + 1] = f4;
}

// ---------------------------------------------------------------------------
extern "C" void kernel_launch(void* const* d_in, const int* in_sizes, int n_in,
                              void* d_out, int out_size) {
    const float* logits = (const float*)d_in[0];
    const int*   tgt    = (const int*)d_in[1];
    (void)in_sizes; (void)n_in; (void)out_size;

    ce_kernel<<<N / 8, 256>>>(logits, tgt);

    // PDL launch of the dependent select kernel: co-scheduled with ce's tail.
    cudaLaunchAttribute attrs[1];
    attrs[0].id = cudaLaunchAttributeProgrammaticStreamSerialization;
    attrs[0].val.programmaticStreamSerializationAllowed = 1;

    cudaLaunchConfig_t cfg = {};
    cfg.gridDim  = {1, 1, 1};
    cfg.blockDim = {1024, 1, 1};
    cfg.dynamicSmemBytes = 0;
    cfg.stream   = 0;           // same (captured) stream as the <<<>>> launch
    cfg.attrs    = attrs;
    cfg.numAttrs = 1;

    cudaError_t err = cudaLaunchKernelEx(&cfg, select_kernel, (float*)d_out);
    if (err != cudaSuccess) {
        // Fallback: plain dependent launch (round-6 behavior).
        cudaGetLastError();     // clear error state
        select_kernel<<<1, 1024>>>((float*)d_out);
    }
}

// round 17
// speedup vs baseline: 1.2182x; 1.0417x over previous
#include <cuda_runtime.h>

static constexpr int N = 32768;
static constexpr int C = 1000;
static constexpr int K_RANK = 9830;        // int(N * 0.3), 0-based descending rank
static constexpr int NB = 8192;            // histogram bins
static constexpr int CAP = 128;            // bucket capacity per bin (max obs ~70)
static constexpr unsigned int KEY_BASE = 0x40000000u >> 12;  // bits(2.0f) >> 12

__device__ unsigned int g_hist[NB];            // counts / bucket slot counters
__device__ float        g_binsum[NB];          // per-bin CE sums
__device__ unsigned int g_bucket[NB * CAP];    // CE bit patterns by bin

// key: 2 exponent bits + 11 mantissa bits over [2.0, 32.0), clamped tails.
// CE = logsumexp - x_t with logits ~ N(0,1): essentially always in [2, 16).
__device__ __forceinline__ int key_of(unsigned int bits) {
    int k = (int)(bits >> 12) - (int)KEY_BASE;
    return min(max(k, 0), NB - 1);
}

// ---------------------------------------------------------------------------
// Kernel 1: per-row CE = log(sum exp(x)) - x[target]; one warp per row.
// Side channel: counting-sort bucket (bits) + per-bin float sum. All atomics
// are one-per-warp, L2-resident, hidden under the HBM-bound mainloop.
// This exact shape measured 6.4 TB/s; every variant tried regressed it.
// ---------------------------------------------------------------------------
__global__ void __launch_bounds__(256) ce_kernel(const float* __restrict__ logits,
                                                 const int*   __restrict__ tgt32) {
    int lane = threadIdx.x & 31;
    int row  = blockIdx.x * 8 + (threadIdx.x >> 5);

    const float*  rowp = logits + (size_t)row * C;
    const float4* r4   = (const float4*)rowp;

    // Front-batch all loads (MLP=8). OOB lanes: -1e30 -> exp underflows to 0.
    float4 v[8];
    #pragma unroll
    for (int j = 0; j < 8; j++) {
        int idx = lane + 32 * j;
        v[j] = (idx < 250) ? r4[idx] : make_float4(-1e30f, -1e30f, -1e30f, -1e30f);
    }

    // dtype detect: odd int32 words of target buffer are zero iff int64-LE
    // (targets < 1000). In-bounds for both layouts.
    unsigned w1 = (unsigned)tgt32[2 * lane + 1];
    unsigned w2 = (unsigned)tgt32[2 * lane + 65];
    bool is32 = __ballot_sync(0xFFFFFFFFu, (w1 | w2) != 0u) != 0u;

    float xt = 0.0f;
    if (lane == 0) {
        int t = is32 ? tgt32[row] : tgt32[2 * row];
        xt = rowp[t];
    }

    float s0 = 0.f, s1 = 0.f, s2 = 0.f, s3 = 0.f;
    #pragma unroll
    for (int j = 0; j < 8; j++) {
        s0 += __expf(v[j].x); s1 += __expf(v[j].y);
        s2 += __expf(v[j].z); s3 += __expf(v[j].w);
    }
    float s = (s0 + s1) + (s2 + s3);
    #pragma unroll
    for (int o = 16; o; o >>= 1) s += __shfl_xor_sync(0xFFFFFFFFu, s, o);

    if (lane == 0) {
        float ce = __logf(s) - xt;
        unsigned int bits = __float_as_uint(ce);
        int bin = key_of(bits);
        unsigned int slot = atomicAdd(&g_hist[bin], 1u);   // returning (slot)
        if (slot < CAP) g_bucket[bin * CAP + slot] = bits;
        atomicAdd(&g_binsum[bin], ce);                     // RED, no return
    }

#if __CUDA_ARCH__ >= 900
    cudaTriggerProgrammaticLaunchCompletion();
#endif
}

// ---------------------------------------------------------------------------
// Kernel 2: single block, 1024 threads, inputs L2-hot (64 KB + one bucket
// row). All global latencies overlapped at the top; candidate rank runs out
// of shared memory. Measured at the grid-1 kernel floor (~7.2-8.8 us) — the
// body is not the binding constraint. Restores scratch invariants for replay.
// ---------------------------------------------------------------------------
__global__ void __launch_bounds__(1024) select_kernel(float* __restrict__ out) {
    __shared__ unsigned int wtot[32], wsufex[32];
    __shared__ float        warp_sums[32];
    __shared__ int          sh_bin, sh_rem, sh_nB;
    __shared__ unsigned int sh_lam;
    __shared__ unsigned int sh_cand[CAP];

#if __CUDA_ARCH__ >= 900
    cudaGridDependencySynchronize();
#endif

    int tid  = threadIdx.x;
    int lane = tid & 31, wid = tid >> 5;

    // Front-batched independent global loads: 8 hist + 8 binsum per thread.
    const uint4*  hp = (const uint4*)g_hist;
    const float4* bp = (const float4*)g_binsum;
    uint4  h0 = hp[tid * 2],  h1 = hp[tid * 2 + 1];
    float4 b0 = bp[tid * 2],  b1 = bp[tid * 2 + 1];

    unsigned int h[8]  = {h0.x, h0.y, h0.z, h0.w, h1.x, h1.y, h1.z, h1.w};
    float        bs[8] = {b0.x, b0.y, b0.z, b0.w, b1.x, b1.y, b1.z, b1.w};

    unsigned int csum = 0;
    #pragma unroll
    for (int j = 0; j < 8; j++) csum += h[j];

    // Two-level inclusive suffix scan over per-thread chunk sums.
    unsigned int sv = csum;
    #pragma unroll
    for (int o = 1; o < 32; o <<= 1) {
        unsigned int nb = __shfl_down_sync(0xFFFFFFFFu, sv, o);
        if (lane + o < 32) sv += nb;
    }
    if (lane == 0) wtot[wid] = sv;
    __syncthreads();
    if (wid == 0) {
        unsigned int w = wtot[lane];
        unsigned int x = w;
        #pragma unroll
        for (int o = 1; o < 32; o <<= 1) {
            unsigned int nb = __shfl_down_sync(0xFFFFFFFFu, x, o);
            if (lane + o < 32) x += nb;
        }
        wsufex[lane] = x - w;
    }
    __syncthreads();

    unsigned int sumGE = sv + wsufex[wid];   // # in bins >= 8*tid
    unsigned int A     = sumGE - csum;       // # in bins >= 8*(tid+1)
    if ((int)A <= K_RANK && K_RANK < (int)(A + csum)) {
        int g = (int)A;
        #pragma unroll
        for (int j = 7; j >= 0; j--) {
            int c = (int)h[j];
            if (K_RANK < g + c) {
                sh_bin = tid * 8 + j;
                sh_rem = K_RANK - g;
                sh_nB  = min(c, CAP);   // hist[B] already in a register here
                break;
            }
            g += c;
        }
    }
    __syncthreads();
    int B   = sh_bin;
    int rem = sh_rem;
    int nB  = sh_nB;

    // Sum of all bins strictly above B (values already in registers).
    float ksum = 0.0f;
    #pragma unroll
    for (int j = 0; j < 8; j++)
        if (tid * 8 + j > B) ksum += bs[j];

    // Stage bucket-B candidates into shared memory (one parallel L2 round).
    if (tid < CAP) sh_cand[tid] = (tid < nB) ? g_bucket[B * CAP + tid] : 0u;
    __syncthreads();

    // Exact tie-safe lambda among candidates; smem broadcast loads only.
    unsigned int myc = (tid < nB) ? sh_cand[tid] : 0u;
    if (tid < nB) {
        int g = 0, e = 0;
        for (int i = 0; i < nB; i++) {
            unsigned int y = sh_cand[i];
            g += (y > myc); e += (y == myc);
        }
        if (g <= rem && rem < g + e) sh_lam = myc;
    }
    __syncthreads();
    if (tid < nB && myc >= sh_lam) ksum += __uint_as_float(myc);

    // Block reduce and write output.
    #pragma unroll
    for (int o = 16; o; o >>= 1) ksum += __shfl_xor_sync(0xFFFFFFFFu, ksum, o);
    if (lane == 0) warp_sums[wid] = ksum;
    __syncthreads();
    if (wid == 0) {
        float t2 = warp_sums[lane];
        #pragma unroll
        for (int o = 16; o; o >>= 1) t2 += __shfl_xor_sync(0xFFFFFFFFu, t2, o);
        if (lane == 0) out[0] = t2 / (float)N;
    }

    // Restore scratch invariants for the next graph replay (vector stores).
    uint4*  hz = (uint4*)g_hist;
    float4* bz = (float4*)g_binsum;
    uint4  z4 = make_uint4(0u, 0u, 0u, 0u);
    float4 f4 = make_float4(0.f, 0.f, 0.f, 0.f);
    hz[tid * 2] = z4;  hz[tid * 2 + 1] = z4;
    bz[tid * 2] = f4;  bz[tid * 2 + 1] = f4;
}

// ---------------------------------------------------------------------------
extern "C" void kernel_launch(void* const* d_in, const int* in_sizes, int n_in,
                              void* d_out, int out_size) {
    const float* logits = (const float*)d_in[0];
    const int*   tgt    = (const int*)d_in[1];
    (void)in_sizes; (void)n_in; (void)out_size;

    ce_kernel<<<N / 8, 256>>>(logits, tgt);

    // PDL launch of the dependent select kernel: co-scheduled with ce's tail.
    cudaLaunchAttribute attrs[1];
    attrs[0].id = cudaLaunchAttributeProgrammaticStreamSerialization;
    attrs[0].val.programmaticStreamSerializationAllowed = 1;

    cudaLaunchConfig_t cfg = {};
    cfg.gridDim  = {1, 1, 1};
    cfg.blockDim = {1024, 1, 1};
    cfg.dynamicSmemBytes = 0;
    cfg.stream   = 0;           // same (captured) stream as the <<<>>> launch
    cfg.attrs    = attrs;
    cfg.numAttrs = 1;

    cudaError_t err = cudaLaunchKernelEx(&cfg, select_kernel, (float*)d_out);
    if (err != cudaSuccess) {
        // Fallback: plain dependent launch (round-6 behavior).
        cudaGetLastError();     // clear error state
        select_kernel<<<1, 1024>>>((float*)d_out);
    }
}